// round 8
// baseline (speedup 1.0000x reference)
#include <cuda_runtime.h>

#define BB 4096
#define TT 512
#define HH 32

typedef unsigned long long u64;

__device__ __forceinline__ u64 pk2(float lo, float hi) {
    u64 r; asm("mov.b64 %0, {%1,%2};" : "=l"(r) : "f"(lo), "f"(hi)); return r;
}
__device__ __forceinline__ void unpk2(u64 v, float& a, float& b) {
    asm("mov.b64 {%0,%1}, %2;" : "=f"(a), "=f"(b) : "l"(v));
}
__device__ __forceinline__ u64 ffma2(u64 a, u64 b, u64 c) {
    u64 d; asm("fma.rn.f32x2 %0, %1, %2, %3;" : "=l"(d) : "l"(a), "l"(b), "l"(c));
    return d;
}
__device__ __forceinline__ u64 fadd2(u64 a, u64 b) {
    u64 d; asm("add.rn.f32x2 %0, %1, %2;" : "=l"(d) : "l"(a), "l"(b));
    return d;
}

// tanh with 2*log2(e) pre-folded: tanh(v) = 1 - 2*rcp(ex2(v') + 1)
__device__ __forceinline__ float tanh_scaled(float vp) {
    float e; asm("ex2.approx.f32 %0, %1;" : "=f"(e) : "f"(vp));
    float r; asm("rcp.approx.f32 %0, %1;" : "=f"(r) : "f"(e + 1.0f));
    return fmaf(-2.0f, r, 1.0f);
}

__global__ void __launch_bounds__(64)
rnn2_kernel(const float* __restrict__ x,       // [B, T, 1]
            const float* __restrict__ hstate,  // [2, B, H]
            const float* __restrict__ Wih0,    // [H, 1]
            const float* __restrict__ Whh0,    // [H, H]
            const float* __restrict__ bih0, const float* __restrict__ bhh0,
            const float* __restrict__ Wih1,    // [H, H]
            const float* __restrict__ Whh1,    // [H, H]
            const float* __restrict__ bih1, const float* __restrict__ bhh1,
            const float* __restrict__ Wfc,     // [1, H]
            const float* __restrict__ bfc,     // [1]
            float* __restrict__ out)           // [B] pred ++ [2,B,H] h_new
{
    // h vectors (single-buffered; all cross-warp hazards bar-separated)
    __shared__ __align__(16) float sh0[2][HH];      // [batch][neuron]
    __shared__ __align__(16) float sh1[2][HH];
    __shared__ __align__(8)  float2 part[2][2][HH]; // [warp][batch][neuron] = (p0,p1)

    const int tid = threadIdx.x;
    const int w   = tid >> 5;            // warp 0/1 = k-half [16w, 16w+16)
    const int j   = tid & 31;            // neuron
    const int b0  = blockIdx.x * 2;

    const float SC = 2.885390081777927f; // 2*log2(e), folded into weights

    // k-half weight slices of row j: 8 u64 per matrix = 48 regs total
    u64 w0h[8], wi1h[8], wh1h[8];
    {
        const float2* p = (const float2*)(Whh0 + j * HH + 16 * w);
        #pragma unroll
        for (int i = 0; i < 8; i++) { float2 f = p[i]; w0h[i]  = pk2(f.x*SC, f.y*SC); }
        p = (const float2*)(Wih1 + j * HH + 16 * w);
        #pragma unroll
        for (int i = 0; i < 8; i++) { float2 f = p[i]; wi1h[i] = pk2(f.x*SC, f.y*SC); }
        p = (const float2*)(Whh1 + j * HH + 16 * w);
        #pragma unroll
        for (int i = 0; i < 8; i++) { float2 f = p[i]; wh1h[i] = pk2(f.x*SC, f.y*SC); }
    }
    const float wx0 = Wih0[j] * SC;
    const float bb0 = (bih0[j] + bhh0[j]) * SC;
    const float bb1 = (bih1[j] + bhh1[j]) * SC;

    if (w == 0) {
        sh0[0][j] = hstate[(size_t)b0 * HH + j];
        sh0[1][j] = hstate[(size_t)(b0 + 1) * HH + j];
    } else {
        sh1[0][j] = hstate[(size_t)BB * HH + (size_t)b0 * HH + j];
        sh1[1][j] = hstate[(size_t)BB * HH + (size_t)(b0 + 1) * HH + j];
    }
    __syncthreads();

    const float* xb[2] = { x + (size_t)b0 * TT, x + (size_t)(b0 + 1) * TT };
    float xv[2] = { xb[0][0], xb[1][0] };

    float p0o[2], p1o[2], h0l[2], h1n[2];

    // ---- prologue: L0(0) only ----
    {
        #pragma unroll
        for (int bi = 0; bi < 2; bi++) {
            u64 a  = (w == 0) ? pk2(fmaf(wx0, xv[bi], bb0), 0.f) : pk2(0.f, 0.f);
            u64 ab = pk2(0.f, 0.f);
            const ulonglong2* hp = ((const ulonglong2*)sh0[bi]) + 4 * w;
            #pragma unroll
            for (int i = 0; i < 4; i++) {
                ulonglong2 v = hp[i];
                a  = ffma2(w0h[2*i],     v.x, a);
                ab = ffma2(w0h[2*i + 1], v.y, ab);
            }
            float lo, hi; unpk2(fadd2(a, ab), lo, hi);
            p0o[bi] = lo + hi;
            part[w][bi][j] = make_float2(p0o[bi], 0.f);
        }
        __syncthreads();
        if (w == 0) {
            #pragma unroll
            for (int bi = 0; bi < 2; bi++)
                sh0[bi][j] = tanh_scaled(p0o[bi] + part[1][bi][j].x);
        }
        __syncthreads();
        xv[0] = xb[0][1]; xv[1] = xb[1][1];
    }

    // ---- mainloop: phase te computes L0(te+1) and L1(te), te = 0..TT-2 ----
    #pragma unroll 1
    for (int te = 0; te < TT - 1; te++) {
        #pragma unroll
        for (int bi = 0; bi < 2; bi++) {
            u64 a0  = (w == 0) ? pk2(fmaf(wx0, xv[bi], bb0), 0.f) : pk2(0.f, 0.f);
            u64 a0b = pk2(0.f, 0.f);
            u64 a1  = (w == 0) ? pk2(bb1, 0.f) : pk2(0.f, 0.f);
            u64 a1b = pk2(0.f, 0.f);
            const ulonglong2* h0p = ((const ulonglong2*)sh0[bi]) + 4 * w;
            const ulonglong2* h1p = ((const ulonglong2*)sh1[bi]) + 4 * w;
            #pragma unroll
            for (int i = 0; i < 4; i++) {
                ulonglong2 v = h0p[i];
                a0  = ffma2(w0h[2*i],      v.x, a0);
                a0b = ffma2(w0h[2*i + 1],  v.y, a0b);
                a1  = ffma2(wi1h[2*i],     v.x, a1);
                a1b = ffma2(wi1h[2*i + 1], v.y, a1b);
            }
            #pragma unroll
            for (int i = 0; i < 4; i++) {
                ulonglong2 u = h1p[i];
                a1  = ffma2(wh1h[2*i],     u.x, a1);
                a1b = ffma2(wh1h[2*i + 1], u.y, a1b);
            }
            float lo, hi;
            unpk2(fadd2(a0, a0b), lo, hi); p0o[bi] = lo + hi;
            unpk2(fadd2(a1, a1b), lo, hi); p1o[bi] = lo + hi;
            part[w][bi][j] = make_float2(p0o[bi], p1o[bi]);
        }
        int tn = te + 2; if (tn > TT - 1) tn = TT - 1;
        xv[0] = xb[0][tn]; xv[1] = xb[1][tn];
        __syncthreads();

        if (w == 0) {           // finish L0: h0'(te+1)
            #pragma unroll
            for (int bi = 0; bi < 2; bi++) {
                h0l[bi] = tanh_scaled(p0o[bi] + part[1][bi][j].x);
                sh0[bi][j] = h0l[bi];
            }
        } else {                // finish L1: h1'(te)
            #pragma unroll
            for (int bi = 0; bi < 2; bi++) {
                h1n[bi] = tanh_scaled(p1o[bi] + part[0][bi][j].y);
                sh1[bi][j] = h1n[bi];
            }
        }
        __syncthreads();
    }

    // ---- epilogue: L1(TT-1) ----
    {
        #pragma unroll
        for (int bi = 0; bi < 2; bi++) {
            u64 a1  = (w == 0) ? pk2(bb1, 0.f) : pk2(0.f, 0.f);
            u64 a1b = pk2(0.f, 0.f);
            const ulonglong2* h0p = ((const ulonglong2*)sh0[bi]) + 4 * w;
            const ulonglong2* h1p = ((const ulonglong2*)sh1[bi]) + 4 * w;
            #pragma unroll
            for (int i = 0; i < 4; i++) {
                ulonglong2 v = h0p[i];
                a1  = ffma2(wi1h[2*i],     v.x, a1);
                a1b = ffma2(wi1h[2*i + 1], v.y, a1b);
            }
            #pragma unroll
            for (int i = 0; i < 4; i++) {
                ulonglong2 u = h1p[i];
                a1  = ffma2(wh1h[2*i],     u.x, a1);
                a1b = ffma2(wh1h[2*i + 1], u.y, a1b);
            }
            float lo, hi; unpk2(fadd2(a1, a1b), lo, hi);
            p1o[bi] = lo + hi;
            part[w][bi][j] = make_float2(0.f, p1o[bi]);
        }
        __syncthreads();
    }

    // ---- outputs ----
    if (w == 0) {
        #pragma unroll
        for (int bi = 0; bi < 2; bi++)
            out[BB + (size_t)(b0 + bi) * HH + j] = h0l[bi];       // h_new[0]
    } else {
        #pragma unroll
        for (int bi = 0; bi < 2; bi++) {
            h1n[bi] = tanh_scaled(p1o[bi] + part[0][bi][j].y);    // h1'(TT-1)
            out[BB + (size_t)BB * HH + (size_t)(b0 + bi) * HH + j] = h1n[bi];
            float p = Wfc[j] * h1n[bi];
            #pragma unroll
            for (int off = 16; off; off >>= 1)
                p += __shfl_xor_sync(0xffffffffu, p, off);
            if (j == 0) out[b0 + bi] = p + bfc[0];                // pred
        }
    }
}

extern "C" void kernel_launch(void* const* d_in, const int* in_sizes, int n_in,
                              void* d_out, int out_size) {
    const float* x     = (const float*)d_in[0];
    const float* hs    = (const float*)d_in[1];
    const float* Wih0  = (const float*)d_in[2];
    const float* Whh0  = (const float*)d_in[3];
    const float* bih0  = (const float*)d_in[4];
    const float* bhh0  = (const float*)d_in[5];
    const float* Wih1  = (const float*)d_in[6];
    const float* Whh1  = (const float*)d_in[7];
    const float* bih1  = (const float*)d_in[8];
    const float* bhh1  = (const float*)d_in[9];
    const float* Wfc   = (const float*)d_in[10];
    const float* bfc   = (const float*)d_in[11];
    float* out = (float*)d_out;

    rnn2_kernel<<<BB / 2, 64>>>(x, hs, Wih0, Whh0, bih0, bhh0,
                                Wih1, Whh1, bih1, bhh1, Wfc, bfc, out);
}

// round 9
// speedup vs baseline: 1.1342x; 1.1342x over previous
#include <cuda_runtime.h>

#define BB 4096
#define TT 512
#define HH 32
#define NB 2

typedef unsigned long long u64;

__device__ __forceinline__ u64 pk2(float lo, float hi) {
    u64 r; asm("mov.b64 %0, {%1,%2};" : "=l"(r) : "f"(lo), "f"(hi)); return r;
}
__device__ __forceinline__ void unpk2(u64 v, float& a, float& b) {
    asm("mov.b64 {%0,%1}, %2;" : "=f"(a), "=f"(b) : "l"(v));
}
__device__ __forceinline__ u64 ffma2(u64 a, u64 b, u64 c) {
    u64 d; asm("fma.rn.f32x2 %0, %1, %2, %3;" : "=l"(d) : "l"(a), "l"(b), "l"(c));
    return d;
}
__device__ __forceinline__ u64 fadd2(u64 a, u64 b) {
    u64 d; asm("add.rn.f32x2 %0, %1, %2;" : "=l"(d) : "l"(a), "l"(b));
    return d;
}

// tanh with 2*log2(e) pre-folded: tanh(v) = 1 - 2*rcp(ex2(v') + 1)
__device__ __forceinline__ float tanh_scaled(float vp) {
    float e; asm("ex2.approx.f32 %0, %1;" : "=f"(e) : "f"(vp));
    float r; asm("rcp.approx.f32 %0, %1;" : "=f"(r) : "f"(e + 1.0f));
    return fmaf(-2.0f, r, 1.0f);
}

__global__ void __launch_bounds__(32, 14)   // 146-reg target -> 14 warps/SM -> ONE wave
rnn2_kernel(const float* __restrict__ x,       // [B, T, 1]
            const float* __restrict__ hstate,  // [2, B, H]
            const float* __restrict__ Wih0,    // [H, 1]
            const float* __restrict__ Whh0,    // [H, H]
            const float* __restrict__ bih0, const float* __restrict__ bhh0,
            const float* __restrict__ Wih1,    // [H, H]
            const float* __restrict__ Whh1,    // [H, H]
            const float* __restrict__ bih1, const float* __restrict__ bhh1,
            const float* __restrict__ Wfc,     // [1, H]
            const float* __restrict__ bfc,     // [1]
            float* __restrict__ out)           // [B] pred ++ [2,B,H] h_new
{
    // 128B rows; all lanes read the same 16B -> broadcast LDS.128.
    __shared__ __align__(16) float sh0[NB][2][HH];
    __shared__ __align__(16) float sh1[NB][2][HH];

    const int j  = threadIdx.x;          // 0..31, one warp per block
    const int b0 = blockIdx.x * NB;

    const float SC = 2.885390081777927f; // 2*log2(e), folded into weights

    // Weight rows for output neuron j, scaled, packed as f32x2 (k, k+1).
    u64 w0[16], wi1[16], wh1[16];
    {
        const float2* p = (const float2*)(Whh0 + j * HH);
        #pragma unroll
        for (int i = 0; i < 16; i++) { float2 f = p[i]; w0[i]  = pk2(f.x*SC, f.y*SC); }
        p = (const float2*)(Wih1 + j * HH);
        #pragma unroll
        for (int i = 0; i < 16; i++) { float2 f = p[i]; wi1[i] = pk2(f.x*SC, f.y*SC); }
        p = (const float2*)(Whh1 + j * HH);
        #pragma unroll
        for (int i = 0; i < 16; i++) { float2 f = p[i]; wh1[i] = pk2(f.x*SC, f.y*SC); }
    }
    const float wx0 = Wih0[j] * SC;
    const float bb0 = (bih0[j] + bhh0[j]) * SC;
    const float bb1 = (bih1[j] + bhh1[j]) * SC;

    #pragma unroll
    for (int bi = 0; bi < NB; bi++) {
        sh0[bi][0][j] = hstate[(size_t)(b0 + bi) * HH + j];
        sh1[bi][0][j] = hstate[(size_t)BB * HH + (size_t)(b0 + bi) * HH + j];
    }
    __syncwarp();

    // Single x base pointer; batch bi at offset bi*TT (saves a pointer reg)
    const float* xb = x + (size_t)b0 * TT;
    float xv[NB];

    // ---- prologue: L0(0): h0'(0) = tanh(Whh0@h0 + Wih0*x0 + b) -> buf 1 ----
    #pragma unroll
    for (int bi = 0; bi < NB; bi++) {
        u64 a  = pk2(fmaf(wx0, xb[bi * TT], bb0), 0.f);
        u64 ab = pk2(0.f, 0.f);
        const ulonglong2* hp = (const ulonglong2*)sh0[bi][0];
        #pragma unroll
        for (int i = 0; i < 8; i++) {
            ulonglong2 v = hp[i];
            a  = ffma2(w0[2*i],     v.x, a);
            ab = ffma2(w0[2*i + 1], v.y, ab);
        }
        float lo, hi;
        unpk2(fadd2(a, ab), lo, hi);
        sh0[bi][1][j] = tanh_scaled(lo + hi);
        xv[bi] = xb[bi * TT + 1];
    }
    __syncwarp();

    // ---- pipelined mainloop: phase t_e computes L0(t_e+1) and L1(t_e) ----
    #pragma unroll 1
    for (int t = 0; t < TT; t += 2) {
        #pragma unroll
        for (int s = 0; s < 2; s++) {     // t_e = t + s; compile-time parity
            const int rb0 = s ^ 1;        // h0'(t_e)
            const int wb0 = s;            // h0'(t_e+1)
            const int rb1 = s;            // h1'(t_e-1)
            const int wb1 = s ^ 1;        // h1'(t_e)

            int tn = t + s + 2; if (tn > TT - 1) tn = TT - 1;  // uniform clamp

            u64 a0[NB], a0b[NB], a1[NB], a1b[NB];
            float xt[NB];
            #pragma unroll
            for (int bi = 0; bi < NB; bi++) {
                a0[bi]  = pk2(fmaf(wx0, xv[bi], bb0), 0.f);
                a0b[bi] = pk2(0.f, 0.f);
                a1[bi]  = pk2(bb1, 0.f);
                a1b[bi] = pk2(0.f, 0.f);
                xt[bi] = xv[bi]; (void)xt[bi];
                xv[bi] = xb[bi * TT + tn];
            }

            // One LDS.128 of h0'(t_e) feeds BOTH Whh0 (L0) and Wih1 (L1)
            #pragma unroll
            for (int i = 0; i < 8; i++) {
                #pragma unroll
                for (int bi = 0; bi < NB; bi++) {
                    ulonglong2 v = ((const ulonglong2*)sh0[bi][rb0])[i];
                    a0[bi]  = ffma2(w0[2*i],      v.x, a0[bi]);
                    a0b[bi] = ffma2(w0[2*i + 1],  v.y, a0b[bi]);
                    a1[bi]  = ffma2(wi1[2*i],     v.x, a1[bi]);
                    a1b[bi] = ffma2(wi1[2*i + 1], v.y, a1b[bi]);
                }
            }
            // Whh1 @ h1'(t_e-1)
            #pragma unroll
            for (int i = 0; i < 8; i++) {
                #pragma unroll
                for (int bi = 0; bi < NB; bi++) {
                    ulonglong2 u = ((const ulonglong2*)sh1[bi][rb1])[i];
                    a1[bi]  = ffma2(wh1[2*i],     u.x, a1[bi]);
                    a1b[bi] = ffma2(wh1[2*i + 1], u.y, a1b[bi]);
                }
            }
            #pragma unroll
            for (int bi = 0; bi < NB; bi++) {
                float lo, hi;
                unpk2(fadd2(a0[bi], a0b[bi]), lo, hi);
                sh0[bi][wb0][j] = tanh_scaled(lo + hi);   // h0'(t_e+1)
                unpk2(fadd2(a1[bi], a1b[bi]), lo, hi);
                sh1[bi][wb1][j] = tanh_scaled(lo + hi);   // h1'(t_e)
            }
            __syncwarp();
        }
    }

    // ---- outputs ----
    // After t_e = TT-1 (s=1): h0'(TT-1) overwritten at t_e=TT-2.. careful:
    // last phase t_e=TT-1 wrote h0'(TT) into wb0=1 (garbage-x clamped, unused)
    // and h1'(TT-1) into sh1[..][wb1=0]. h0'(TT-1) lives in sh0[..][rb0 of
    // last phase] = sh0[..][0].
    #pragma unroll
    for (int bi = 0; bi < NB; bi++) {
        const size_t ob = (size_t)(b0 + bi) * HH + j;
        float h0l = sh0[bi][0][j];
        float h1l = sh1[bi][0][j];
        out[BB + ob]                   = h0l;    // h_new[0]
        out[BB + (size_t)BB * HH + ob] = h1l;    // h_new[1]

        float p = Wfc[j] * h1l;
        #pragma unroll
        for (int off = 16; off; off >>= 1)
            p += __shfl_xor_sync(0xffffffffu, p, off);
        if (j == 0) out[b0 + bi] = p + bfc[0];
    }
}

extern "C" void kernel_launch(void* const* d_in, const int* in_sizes, int n_in,
                              void* d_out, int out_size) {
    const float* x     = (const float*)d_in[0];
    const float* hs    = (const float*)d_in[1];
    const float* Wih0  = (const float*)d_in[2];
    const float* Whh0  = (const float*)d_in[3];
    const float* bih0  = (const float*)d_in[4];
    const float* bhh0  = (const float*)d_in[5];
    const float* Wih1  = (const float*)d_in[6];
    const float* Whh1  = (const float*)d_in[7];
    const float* bih1  = (const float*)d_in[8];
    const float* bhh1  = (const float*)d_in[9];
    const float* Wfc   = (const float*)d_in[10];
    const float* bfc   = (const float*)d_in[11];
    float* out = (float*)d_out;

    rnn2_kernel<<<BB / NB, 32>>>(x, hs, Wih0, Whh0, bih0, bhh0,
                                 Wih1, Whh1, bih1, bhh1, Wfc, bfc, out);
}